// round 3
// baseline (speedup 1.0000x reference)
#include <cuda_runtime.h>
#include <cuda_fp16.h>
#include <cstdint>
#include <cstddef>

// y[M,N] = x[M,K] @ W[N,K]^T * scale + bias   M=16384, N=4096, K=4096
// Build target is sm_103 (no 'a') -> tcgen05 unavailable; use mma.sync HMMA.
// x fp32->fp16 scratch, w int32->fp16 (ints <127 exact), fp32 accumulate.

#define MM 16384
#define NN 4096
#define KK 4096

#define TILE_M 128
#define TILE_N 256
#define KC 64                  // halves per K-chunk = 128 bytes per row
#define STAGES 4
#define NCHUNK (KK / KC)       // 64
#define GTHREADS 256

// warp tiling: 2 (M) x 4 (N) warps, each 64x64
#define WARP_M 64
#define WARP_N 64
#define MT 4                   // m16 tiles per warp
#define NT 8                   // n8 tiles per warp

__device__ __half g_xh[(size_t)MM * KK];   // 128 MB scratch
__device__ __half g_wh[(size_t)NN * KK];   // 32 MB scratch (L2 resident)

#define A_BYTES (TILE_M * 128)             // 16 KB / stage
#define B_BYTES (TILE_N * 128)             // 32 KB / stage
#define STAGE_BYTES (A_BYTES + B_BYTES)    // 48 KB
#define SMEM_TOTAL (STAGES * STAGE_BYTES)  // 192 KB

#define SWZ(o) ((o) ^ (((o) >> 3) & 0x70))

__device__ __forceinline__ uint32_t s2u(const void* p) {
    uint32_t a;
    asm("{ .reg .u64 t; cvta.to.shared.u64 t, %1; cvt.u32.u64 %0, t; }" : "=r"(a) : "l"(p));
    return a;
}

__device__ __forceinline__ void cp16(uint32_t dst, const void* src) {
    asm volatile("cp.async.cg.shared.global [%0], [%1], 16;" :: "r"(dst), "l"(src) : "memory");
}

__device__ __forceinline__ void ldsm_x4(uint32_t* r, uint32_t addr) {
    asm volatile("ldmatrix.sync.aligned.m8n8.x4.shared.b16 {%0,%1,%2,%3}, [%4];"
                 : "=r"(r[0]), "=r"(r[1]), "=r"(r[2]), "=r"(r[3]) : "r"(addr));
}

__device__ __forceinline__ void mma16816(float* c, const uint32_t* a, const uint32_t* b) {
    asm volatile(
        "mma.sync.aligned.m16n8k16.row.col.f32.f16.f16.f32 "
        "{%0,%1,%2,%3}, {%4,%5,%6,%7}, {%8,%9}, {%0,%1,%2,%3};"
        : "+f"(c[0]), "+f"(c[1]), "+f"(c[2]), "+f"(c[3])
        : "r"(a[0]), "r"(a[1]), "r"(a[2]), "r"(a[3]), "r"(b[0]), "r"(b[1]));
}

// ---------------- conversion kernels ----------------------------------------
struct h4 { __half2 a, b; };

__global__ void cvt_x_kernel(const float4* __restrict__ x) {
    size_t i = (size_t)blockIdx.x * blockDim.x + threadIdx.x;
    float4 v = x[i];
    h4 o;
    o.a = __floats2half2_rn(v.x, v.y);
    o.b = __floats2half2_rn(v.z, v.w);
    reinterpret_cast<h4*>(g_xh)[i] = o;
}

__global__ void cvt_w_kernel(const int4* __restrict__ w) {
    size_t i = (size_t)blockIdx.x * blockDim.x + threadIdx.x;
    int4 v = w[i];
    h4 o;
    o.a = __halves2half2(__int2half_rn(v.x), __int2half_rn(v.y));
    o.b = __halves2half2(__int2half_rn(v.z), __int2half_rn(v.w));
    reinterpret_cast<h4*>(g_wh)[i] = o;
}

// ---------------- GEMM -------------------------------------------------------
__global__ void __launch_bounds__(GTHREADS, 1)
gemm_kernel(const float* __restrict__ scale, const float* __restrict__ bias,
            float* __restrict__ out) {
    extern __shared__ char smem[];
    const uint32_t sbase = s2u(smem);
    const int tid = threadIdx.x;
    const int wid = tid >> 5, lane = tid & 31;
    const int n0 = blockIdx.x * TILE_N;
    const int m0 = blockIdx.y * TILE_M;
    const int wm = (wid >> 2) * WARP_M;     // warp M origin in tile
    const int wn = (wid & 3) * WARP_N;      // warp N origin in tile

    // ---- stage loader ----
    auto load_chunk = [&](int chunk, int buf) {
        const uint32_t a_s = sbase + buf * STAGE_BYTES;
        const uint32_t b_s = a_s + A_BYTES;
        const size_t k0 = (size_t)chunk * KC;
        #pragma unroll
        for (int j = 0; j < 4; j++) {               // A: 128 rows x 8 x 16B
            int idx = tid + GTHREADS * j;
            int row = idx >> 3, kb = (idx & 7) * 16;
            cp16(a_s + SWZ(row * 128 + kb),
                 g_xh + (size_t)(m0 + row) * KK + k0 + (kb >> 1));
        }
        #pragma unroll
        for (int j = 0; j < 8; j++) {               // B: 256 rows x 8 x 16B
            int idx = tid + GTHREADS * j;
            int row = idx >> 3, kb = (idx & 7) * 16;
            cp16(b_s + SWZ(row * 128 + kb),
                 g_wh + (size_t)(n0 + row) * KK + k0 + (kb >> 1));
        }
        asm volatile("cp.async.commit_group;" ::: "memory");
    };

    float acc[MT][NT][4];
    #pragma unroll
    for (int i = 0; i < MT; i++)
        #pragma unroll
        for (int j = 0; j < NT; j++)
            #pragma unroll
            for (int c = 0; c < 4; c++) acc[i][j][c] = 0.f;

    #pragma unroll
    for (int s = 0; s < STAGES - 1; s++) load_chunk(s, s);

    // per-lane ldmatrix row components (byte offsets within row handled per-ks)
    const int a_row = wm + (lane & 15);             // + mt*16
    const int a_kb  = (lane >> 4) * 16;
    const int b_row = wn + ((lane >> 4) << 3) + (lane & 7);  // + j*16 (x4 covers 2 n-tiles)
    const int b_kb  = ((lane >> 3) & 1) * 16;

    for (int i = 0; i < NCHUNK; i++) {
        const int buf = i & (STAGES - 1);
        asm volatile("cp.async.wait_group %0;" :: "n"(STAGES - 2) : "memory");
        __syncthreads();

        const uint32_t a_s = sbase + buf * STAGE_BYTES;
        const uint32_t b_s = a_s + A_BYTES;

        #pragma unroll
        for (int ks = 0; ks < 4; ks++) {            // 4 x k16 per chunk
            uint32_t af[MT][4], bf[4][4];
            #pragma unroll
            for (int mt = 0; mt < MT; mt++)
                ldsm_x4(af[mt], a_s + SWZ((a_row + mt * 16) * 128 + ks * 32 + a_kb));
            #pragma unroll
            for (int j = 0; j < 4; j++)             // each covers n-tiles 2j, 2j+1
                ldsm_x4(bf[j], b_s + SWZ((b_row + j * 16) * 128 + ks * 32 + b_kb));
            #pragma unroll
            for (int mt = 0; mt < MT; mt++)
                #pragma unroll
                for (int nt = 0; nt < NT; nt++)
                    mma16816(acc[mt][nt], af[mt], bf[nt >> 1] + (nt & 1) * 2);
        }

        if (i + STAGES - 1 < NCHUNK) load_chunk(i + STAGES - 1, buf == 0 ? STAGES - 1 : buf - 1);
    }

    // ---- epilogue: scale + bias, direct reg -> gmem ----
    const float scl = __ldg(scale);
    const int gid = lane >> 2, tq = lane & 3;       // frag row group / col pair
    #pragma unroll
    for (int mt = 0; mt < MT; mt++) {
        const size_t r0 = (size_t)(m0 + wm + mt * 16 + gid) * NN;
        const size_t r1 = r0 + 8 * NN;
        #pragma unroll
        for (int nt = 0; nt < NT; nt++) {
            const int col = n0 + wn + nt * 8 + tq * 2;
            const float2 bv = *reinterpret_cast<const float2*>(bias + col);
            float2 v0, v1;
            v0.x = acc[mt][nt][0] * scl + bv.x;
            v0.y = acc[mt][nt][1] * scl + bv.y;
            v1.x = acc[mt][nt][2] * scl + bv.x;
            v1.y = acc[mt][nt][3] * scl + bv.y;
            *reinterpret_cast<float2*>(out + r0 + col) = v0;
            *reinterpret_cast<float2*>(out + r1 + col) = v1;
        }
    }
}

// ---------------- launch -----------------------------------------------------
extern "C" void kernel_launch(void* const* d_in, const int* in_sizes, int n_in,
                              void* d_out, int out_size) {
    const float* x     = (const float*)d_in[0];
    const int*   wq    = (const int*)d_in[1];
    const float* scale = (const float*)d_in[2];
    const float* bias  = (const float*)d_in[3];
    float* out = (float*)d_out;

    cvt_x_kernel<<<16777216 / 256, 256>>>(reinterpret_cast<const float4*>(x));
    cvt_w_kernel<<<4194304 / 256, 256>>>(reinterpret_cast<const int4*>(wq));

    static bool attr_set = false;
    if (!attr_set) {
        cudaFuncSetAttribute(gemm_kernel, cudaFuncAttributeMaxDynamicSharedMemorySize,
                             SMEM_TOTAL);
        attr_set = true;
    }
    dim3 grid(NN / TILE_N, MM / TILE_M);   // (16, 128): N fastest -> W stays L2-hot
    gemm_kernel<<<grid, GTHREADS, SMEM_TOTAL>>>(scale, bias, out);
}

// round 5
// speedup vs baseline: 2.2526x; 2.2526x over previous
#include <cuda_runtime.h>
#include <cuda_fp16.h>
#include <cstdint>
#include <cstddef>

// y[M,N] = x[M,K] @ W[N,K]^T * scale + bias   M=16384, N=4096, K=4096
// Dual path: tcgen05 (sm_103a feature-guarded) / mma.sync HMMA fallback.
// x fp32->fp16 scratch, w int32->fp16 (ints <127 exact), fp32 accumulate.
// R4 fix: cp.async tail race — wait_group(0) once no newer groups exist.

#define MM 16384
#define NN 4096
#define KK 4096

#define TILE_M 128
#define TILE_N 256
#define KC 64                  // halves per K-chunk = 128 bytes per row
#define STAGES 4
#define NCHUNK (KK / KC)       // 64
#define GTHREADS 256

// HMMA warp tiling: 2 (M) x 4 (N) warps, each 64x64
#define WARP_M 64
#define WARP_N 64
#define MT 4
#define NT 8

__device__ __half g_xh[(size_t)MM * KK];   // 128 MB scratch
__device__ __half g_wh[(size_t)NN * KK];   // 32 MB scratch (L2 resident)

#define A_BYTES (TILE_M * 128)             // 16 KB / stage
#define B_BYTES (TILE_N * 128)             // 32 KB / stage
#define STAGE_BYTES (A_BYTES + B_BYTES)    // 48 KB
#define SMEM_TOTAL (1024 + STAGES * STAGE_BYTES)   // 197632

#define SWZ(o) ((o) ^ (((o) >> 3) & 0x70))

__device__ __forceinline__ uint32_t s2u(const void* p) {
    uint32_t a;
    asm("{ .reg .u64 t; cvta.to.shared.u64 t, %1; cvt.u32.u64 %0, t; }" : "=r"(a) : "l"(p));
    return a;
}

__device__ __forceinline__ void cp16(uint32_t dst, const void* src) {
    asm volatile("cp.async.cg.shared.global [%0], [%1], 16;" :: "r"(dst), "l"(src) : "memory");
}

// ---------------- HMMA helpers ----------------------------------------------
__device__ __forceinline__ void ldsm_x4(uint32_t* r, uint32_t addr) {
    asm volatile("ldmatrix.sync.aligned.m8n8.x4.shared.b16 {%0,%1,%2,%3}, [%4];"
                 : "=r"(r[0]), "=r"(r[1]), "=r"(r[2]), "=r"(r[3]) : "r"(addr));
}

__device__ __forceinline__ void mma16816(float* c, const uint32_t* a, const uint32_t* b) {
    asm volatile(
        "mma.sync.aligned.m16n8k16.row.col.f32.f16.f16.f32 "
        "{%0,%1,%2,%3}, {%4,%5,%6,%7}, {%8,%9}, {%0,%1,%2,%3};"
        : "+f"(c[0]), "+f"(c[1]), "+f"(c[2]), "+f"(c[3])
        : "r"(a[0]), "r"(a[1]), "r"(a[2]), "r"(a[3]), "r"(b[0]), "r"(b[1]));
}

// ---------------- tcgen05 helpers --------------------------------------------
#define MBAR_INIT(a, c) \
    asm volatile("mbarrier.init.shared.b64 [%0], %1;" :: "r"(a), "r"(c) : "memory")

#define MBAR_WAIT(a, par) do {                                                  \
    uint32_t _m = (a), _p = (par);                                              \
    asm volatile(                                                               \
        "{\n\t.reg .pred P1;\n\t"                                               \
        "WL_%=:\n\t"                                                            \
        "mbarrier.try_wait.parity.acquire.cta.shared::cta.b64 P1, [%0], %1, 0x989680;\n\t" \
        "@P1 bra.uni WD_%=;\n\t"                                                \
        "bra.uni WL_%=;\n\t"                                                    \
        "WD_%=:\n\t}"                                                           \
        :: "r"(_m), "r"(_p) : "memory");                                        \
} while (0)

#define TC_COMMIT(a) \
    asm volatile("tcgen05.commit.cta_group::1.mbarrier::arrive::one.shared::cluster.b64 [%0];" \
                 :: "r"(a) : "memory")
#define TC_ALLOC(sa, n) \
    asm volatile("tcgen05.alloc.cta_group::1.sync.aligned.shared::cta.b32 [%0], %1;" \
                 :: "r"(sa), "r"((uint32_t)(n)) : "memory")
#define TC_DEALLOC(t, n) \
    asm volatile("tcgen05.dealloc.cta_group::1.sync.aligned.b32 %0, %1;" :: "r"(t), "r"((uint32_t)(n)))
#define TC_RELINQ() \
    asm volatile("tcgen05.relinquish_alloc_permit.cta_group::1.sync.aligned;")
#define TC_FENCE_AFTER()  asm volatile("tcgen05.fence::after_thread_sync;" ::: "memory")
#define TC_FENCE_BEFORE() asm volatile("tcgen05.fence::before_thread_sync;" ::: "memory")
#define TC_WAIT_LD()      asm volatile("tcgen05.wait::ld.sync.aligned;" ::: "memory")
#define FENCE_ASYNC()     asm volatile("fence.proxy.async.shared::cta;" ::: "memory")

#define LDTM_X32(r, ta)                                                         \
    asm volatile(                                                               \
        "tcgen05.ld.sync.aligned.32x32b.x32.b32 "                               \
        "{%0, %1, %2, %3, %4, %5, %6, %7, "                                     \
        " %8, %9, %10, %11, %12, %13, %14, %15, "                               \
        " %16, %17, %18, %19, %20, %21, %22, %23, "                             \
        " %24, %25, %26, %27, %28, %29, %30, %31}, [%32];"                      \
        : "=r"((r)[0]),  "=r"((r)[1]),  "=r"((r)[2]),  "=r"((r)[3]),            \
          "=r"((r)[4]),  "=r"((r)[5]),  "=r"((r)[6]),  "=r"((r)[7]),            \
          "=r"((r)[8]),  "=r"((r)[9]),  "=r"((r)[10]), "=r"((r)[11]),           \
          "=r"((r)[12]), "=r"((r)[13]), "=r"((r)[14]), "=r"((r)[15]),           \
          "=r"((r)[16]), "=r"((r)[17]), "=r"((r)[18]), "=r"((r)[19]),           \
          "=r"((r)[20]), "=r"((r)[21]), "=r"((r)[22]), "=r"((r)[23]),           \
          "=r"((r)[24]), "=r"((r)[25]), "=r"((r)[26]), "=r"((r)[27]),           \
          "=r"((r)[28]), "=r"((r)[29]), "=r"((r)[30]), "=r"((r)[31])            \
        : "r"(ta))

// ---------------- conversion kernels ----------------------------------------
struct h4 { __half2 a, b; };

__global__ void cvt_x_kernel(const float4* __restrict__ x) {
    size_t i = (size_t)blockIdx.x * blockDim.x + threadIdx.x;
    float4 v = x[i];
    h4 o;
    o.a = __floats2half2_rn(v.x, v.y);
    o.b = __floats2half2_rn(v.z, v.w);
    reinterpret_cast<h4*>(g_xh)[i] = o;
}

__global__ void cvt_w_kernel(const int4* __restrict__ w) {
    size_t i = (size_t)blockIdx.x * blockDim.x + threadIdx.x;
    int4 v = w[i];
    h4 o;
    o.a = __halves2half2(__int2half_rn(v.x), __int2half_rn(v.y));
    o.b = __halves2half2(__int2half_rn(v.z), __int2half_rn(v.w));
    reinterpret_cast<h4*>(g_wh)[i] = o;
}

// ---------------- GEMM -------------------------------------------------------
__global__ void __launch_bounds__(GTHREADS, 1)
gemm_kernel(const float* __restrict__ scale, const float* __restrict__ bias,
            float* __restrict__ out) {
    extern __shared__ char smem[];
    const uint32_t sbase = s2u(smem);
    const int tid = threadIdx.x;
    const int wid = tid >> 5, lane = tid & 31;
    const int n0 = blockIdx.x * TILE_N;
    const int m0 = blockIdx.y * TILE_M;

#if defined(__CUDA_ARCH__) && defined(__CUDA_ARCH_FEAT_SM103_ALL)
    // ======================= tcgen05 path (sm_103a) ==========================
    if (wid == 0) TC_ALLOC(sbase + 0, 256);
    if (tid == 0) {
        #pragma unroll
        for (int s = 0; s < STAGES; s++) MBAR_INIT(sbase + 8 + 8 * s, 1);
    }
    __syncthreads();
    uint32_t tmem;
    asm volatile("ld.shared.b32 %0, [%1];" : "=r"(tmem) : "r"(sbase + 0));

    const uint32_t idesc = (1u << 4) | ((TILE_N / 8) << 17) | ((TILE_M / 16) << 24);
    const uint64_t desc_base = (uint64_t(2) << 61) | (uint64_t(1) << 46)
                             | (uint64_t(64) << 32) | (uint64_t(1) << 16);

    auto load_chunk = [&](int chunk, int buf) {
        const uint32_t a_s = sbase + 1024 + buf * STAGE_BYTES;
        const uint32_t b_s = a_s + A_BYTES;
        const size_t k0 = (size_t)chunk * KC;
        #pragma unroll
        for (int j = 0; j < 4; j++) {               // A: 128 rows x 8 x 16B
            int idx = tid + GTHREADS * j;
            int row = idx >> 3, kb = (idx & 7) * 16;
            cp16(a_s + SWZ(row * 128 + kb),
                 g_xh + (size_t)(m0 + row) * KK + k0 + (kb >> 1));
        }
        #pragma unroll
        for (int j = 0; j < 8; j++) {               // B: 256 rows x 8 x 16B
            int idx = tid + GTHREADS * j;
            int row = idx >> 3, kb = (idx & 7) * 16;
            cp16(b_s + SWZ(row * 128 + kb),
                 g_wh + (size_t)(n0 + row) * KK + k0 + (kb >> 1));
        }
        asm volatile("cp.async.commit_group;" ::: "memory");
    };

    // prologue: chunks 0, 1 (load lead = 2)
    load_chunk(0, 0);
    load_chunk(1, 1);

    for (int i = 0; i < NCHUNK; i++) {
        const int buf = i & (STAGES - 1);
        // retire chunk i's cp group. While newer groups are still being
        // issued, {i, i+1} are pending -> wait_group(1) retires i. Once the
        // last chunk has been issued (i >= NCHUNK-2) there may be only one
        // pending group, so wait_group(1) would NOT retire it -> wait_group(0).
        if (i < NCHUNK - 2) {
            asm volatile("cp.async.wait_group 1;" ::: "memory");
        } else {
            asm volatile("cp.async.wait_group 0;" ::: "memory");
        }
        __syncthreads();
        FENCE_ASYNC();
        if (tid == 0) {
            const uint32_t a_s = sbase + 1024 + buf * STAGE_BYTES;
            uint64_t ad = desc_base | ((a_s >> 4) & 0x3FFF);
            uint64_t bd = desc_base | (((a_s + A_BYTES) >> 4) & 0x3FFF);
            #pragma unroll
            for (int ks = 0; ks < 4; ks++)
                asm volatile(
                    "{\n\t.reg .pred p;\n\tsetp.ne.u32 p, %5, 0;\n\t"
                    "tcgen05.mma.cta_group::1.kind::f16 [%0], %1, %2, %3, {%4, %4, %4, %4}, p;\n\t}"
                    :: "r"(tmem), "l"(ad + ks * 2), "l"(bd + ks * 2), "r"(idesc),
                       "r"(0u), "r"((i == 0 && ks == 0) ? 0u : 1u) : "memory");
            TC_COMMIT(sbase + 8 + 8 * buf);
        }
        // load chunk i+2: its buffer was used by chunk i-2 -> wait its MMA
        if (i + 2 < NCHUNK) {
            if (i >= 2)
                MBAR_WAIT(sbase + 8 + 8 * ((i - 2) & (STAGES - 1)), ((i - 2) / STAGES) & 1);
            load_chunk(i + 2, (i + 2) & (STAGES - 1));
        }
    }

    // wait for last chunk's MMA (in-order completion covers all prior)
    MBAR_WAIT(sbase + 8 + 8 * ((NCHUNK - 1) & (STAGES - 1)),
              ((NCHUNK - 1) / STAGES) & 1);
    TC_FENCE_AFTER();

    if (wid < 4) {
        const float scl = __ldg(scale);
        const int m = m0 + wid * 32 + lane;
        #pragma unroll
        for (int base = 0; base < TILE_N; base += 32) {
            uint32_t r[32];
            LDTM_X32(r, tmem + base);
            TC_WAIT_LD();
            float4* op = reinterpret_cast<float4*>(out + (size_t)m * NN + n0 + base);
            #pragma unroll
            for (int c = 0; c < 32; c += 4) {
                float4 v;
                v.x = __uint_as_float(r[c + 0]) * scl + __ldg(&bias[n0 + base + c + 0]);
                v.y = __uint_as_float(r[c + 1]) * scl + __ldg(&bias[n0 + base + c + 1]);
                v.z = __uint_as_float(r[c + 2]) * scl + __ldg(&bias[n0 + base + c + 2]);
                v.w = __uint_as_float(r[c + 3]) * scl + __ldg(&bias[n0 + base + c + 3]);
                op[c >> 2] = v;
            }
        }
        TC_FENCE_BEFORE();
    }
    __syncthreads();
    if (wid == 0) {
        TC_RELINQ();
        TC_DEALLOC(tmem, 256);
    }

#else
    // ======================= HMMA fallback ===================================
    const int wm = (wid >> 2) * WARP_M;
    const int wn = (wid & 3) * WARP_N;

    auto load_chunk = [&](int chunk, int buf) {
        const uint32_t a_s = sbase + buf * STAGE_BYTES;
        const uint32_t b_s = a_s + A_BYTES;
        const size_t k0 = (size_t)chunk * KC;
        #pragma unroll
        for (int j = 0; j < 4; j++) {
            int idx = tid + GTHREADS * j;
            int row = idx >> 3, kb = (idx & 7) * 16;
            cp16(a_s + SWZ(row * 128 + kb),
                 g_xh + (size_t)(m0 + row) * KK + k0 + (kb >> 1));
        }
        #pragma unroll
        for (int j = 0; j < 8; j++) {
            int idx = tid + GTHREADS * j;
            int row = idx >> 3, kb = (idx & 7) * 16;
            cp16(b_s + SWZ(row * 128 + kb),
                 g_wh + (size_t)(n0 + row) * KK + k0 + (kb >> 1));
        }
        asm volatile("cp.async.commit_group;" ::: "memory");
    };

    float acc[MT][NT][4];
    #pragma unroll
    for (int i = 0; i < MT; i++)
        #pragma unroll
        for (int j = 0; j < NT; j++)
            #pragma unroll
            for (int c = 0; c < 4; c++) acc[i][j][c] = 0.f;

    #pragma unroll
    for (int s = 0; s < STAGES - 1; s++) load_chunk(s, s);

    const int a_row = wm + (lane & 15);
    const int a_kb  = (lane >> 4) * 16;
    const int b_row = wn + ((lane >> 4) << 3) + (lane & 7);
    const int b_kb  = ((lane >> 3) & 1) * 16;

    for (int i = 0; i < NCHUNK; i++) {
        const int buf = i & (STAGES - 1);
        // same tail-race fix: once the last load has been issued there may be
        // fewer than STAGES-1 pending groups -> wait_group(0)
        if (i < NCHUNK - 3) {
            asm volatile("cp.async.wait_group 2;" ::: "memory");
        } else {
            asm volatile("cp.async.wait_group 0;" ::: "memory");
        }
        __syncthreads();

        const uint32_t a_s = sbase + buf * STAGE_BYTES;
        const uint32_t b_s = a_s + A_BYTES;

        #pragma unroll
        for (int ks = 0; ks < 4; ks++) {
            uint32_t af[MT][4], bf[4][4];
            #pragma unroll
            for (int mt = 0; mt < MT; mt++)
                ldsm_x4(af[mt], a_s + SWZ((a_row + mt * 16) * 128 + ks * 32 + a_kb));
            #pragma unroll
            for (int j = 0; j < 4; j++)
                ldsm_x4(bf[j], b_s + SWZ((b_row + j * 16) * 128 + ks * 32 + b_kb));
            #pragma unroll
            for (int mt = 0; mt < MT; mt++)
                #pragma unroll
                for (int nt = 0; nt < NT; nt++)
                    mma16816(acc[mt][nt], af[mt], bf[nt >> 1] + (nt & 1) * 2);
        }

        if (i + STAGES - 1 < NCHUNK) load_chunk(i + STAGES - 1, buf == 0 ? STAGES - 1 : buf - 1);
    }

    const float scl = __ldg(scale);
    const int gid = lane >> 2, tq = lane & 3;
    #pragma unroll
    for (int mt = 0; mt < MT; mt++) {
        const size_t r0 = (size_t)(m0 + wm + mt * 16 + gid) * NN;
        const size_t r1 = r0 + 8 * NN;
        #pragma unroll
        for (int nt = 0; nt < NT; nt++) {
            const int col = n0 + wn + nt * 8 + tq * 2;
            const float2 bv = *reinterpret_cast<const float2*>(bias + col);
            float2 v0, v1;
            v0.x = acc[mt][nt][0] * scl + bv.x;
            v0.y = acc[mt][nt][1] * scl + bv.y;
            v1.x = acc[mt][nt][2] * scl + bv.x;
            v1.y = acc[mt][nt][3] * scl + bv.y;
            *reinterpret_cast<float2*>(out + r0 + col) = v0;
            *reinterpret_cast<float2*>(out + r1 + col) = v1;
        }
    }
#endif
}

// ---------------- launch -----------------------------------------------------
extern "C" void kernel_launch(void* const* d_in, const int* in_sizes, int n_in,
                              void* d_out, int out_size) {
    const float* x     = (const float*)d_in[0];
    const int*   wq    = (const int*)d_in[1];
    const float* scale = (const float*)d_in[2];
    const float* bias  = (const float*)d_in[3];
    float* out = (float*)d_out;

    cvt_x_kernel<<<16777216 / 256, 256>>>(reinterpret_cast<const float4*>(x));
    cvt_w_kernel<<<4194304 / 256, 256>>>(reinterpret_cast<const int4*>(wq));

    static bool attr_set = false;
    if (!attr_set) {
        cudaFuncSetAttribute(gemm_kernel, cudaFuncAttributeMaxDynamicSharedMemorySize,
                             SMEM_TOTAL);
        attr_set = true;
    }
    dim3 grid(NN / TILE_N, MM / TILE_M);   // (16, 128): N fastest -> W stays L2-hot
    gemm_kernel<<<grid, GTHREADS, SMEM_TOTAL>>>(scale, bias, out);
}